// round 14
// baseline (speedup 1.0000x reference)
#include <cuda_runtime.h>
#include <cuda_fp16.h>
#include <cstdint>

#define EXPERTS 8
#define HID     2048
#define INTER   4096
#define TWO_I   8192
#define TOK     1024
#define NPAIR   2048
#define GSIZE   128

// ---------------------------------------------------------------------------
// Scratch (static __device__ globals)
// ---------------------------------------------------------------------------
__device__ __half g_hh[(size_t)NPAIR * INTER];   // h = gelu(gate)*up, fp16
__device__ __half g_xh[(size_t)TOK * HID];       // x rounded to fp16
__device__ float  g_S0[TOK][HID / GSIZE];        // group sums of fp16(x)
__device__ float  g_S1[NPAIR][INTER / GSIZE];    // group sums of fp16(h)
__device__ float  g_dn[(size_t)NPAIR * HID];
__device__ int    g_cnt[EXPERTS];
__device__ int    g_list[EXPERTS][NPAIR];
__device__ float  g_coef[NPAIR];

__device__ int g_wmode, g_swap_gu, g_swap_dn, g_swap_rt;

// ---------------------------------------------------------------------------
// helpers
// ---------------------------------------------------------------------------
__device__ __forceinline__ uint32_t smaddr(const void* p) {
    return (uint32_t)__cvta_generic_to_shared(p);
}
__device__ __forceinline__ void cp16(uint32_t dst, const void* src, int srcbytes) {
    asm volatile("cp.async.cg.shared.global [%0], [%1], 16, %2;"
                 :: "r"(dst), "l"(src), "r"(srcbytes));
}
__device__ __forceinline__ void ldsm4(uint32_t& a0, uint32_t& a1,
                                      uint32_t& a2, uint32_t& a3, uint32_t addr) {
    asm volatile("ldmatrix.sync.aligned.m8n8.x4.shared.b16 {%0,%1,%2,%3}, [%4];"
                 : "=r"(a0), "=r"(a1), "=r"(a2), "=r"(a3) : "r"(addr));
}
__device__ __forceinline__ void mma_f16(float c[4],
    uint32_t a0, uint32_t a1, uint32_t a2, uint32_t a3, uint32_t b0, uint32_t b1)
{
    asm volatile(
        "mma.sync.aligned.m16n8k16.row.col.f32.f16.f16.f32 "
        "{%0,%1,%2,%3}, {%4,%5,%6,%7}, {%8,%9}, {%0,%1,%2,%3};\n"
        : "+f"(c[0]), "+f"(c[1]), "+f"(c[2]), "+f"(c[3])
        : "r"(a0), "r"(a1), "r"(a2), "r"(a3), "r"(b0), "r"(b1));
}
__device__ __forceinline__ float fast_tanh(float x) {
    float e, inv;
    float ax = fabsf(x) * 2.8853900817779268f;
    asm("ex2.approx.f32 %0, %1;" : "=f"(e) : "f"(ax));
    asm("rcp.approx.f32 %0, %1;" : "=f"(inv) : "f"(e + 1.f));
    return copysignf(1.f - 2.f * inv, x);
}

// ---------------------------------------------------------------------------
// Setup kernels
// ---------------------------------------------------------------------------
__global__ void k_detect(const uint32_t* __restrict__ gup,
                         const float* __restrict__ gus_a,
                         const float* __restrict__ dns_a,
                         const uint32_t* __restrict__ rt_a)
{
    if (threadIdx.x < EXPERTS) g_cnt[threadIdx.x] = 0;
    if (threadIdx.x != 0) return;
    int widened = 1;
    for (int i = 0; i < 16; i++)
        if (gup[i] & 0xFFFFFF00u) widened = 0;
    g_wmode = widened;
    int neg = 0;
    for (int i = 0; i < 9; i++) neg += (gus_a[i] < 0.f) ? 1 : 0;
    g_swap_gu = (neg > 4) ? 1 : 0;
    neg = 0;
    for (int i = 0; i < 9; i++) neg += (dns_a[i] < 0.f) ? 1 : 0;
    g_swap_dn = (neg > 4) ? 1 : 0;
    int small = 1;
    for (int i = 0; i < 16; i++)
        if (rt_a[i] >= 256u) small = 0;
    g_swap_rt = small ? 0 : 1;
}

__global__ void k_route(const void* __restrict__ a, const void* __restrict__ b) {
    const int*   ridx = (const int*)  (g_swap_rt ? b : a);
    const float* rw   = (const float*)(g_swap_rt ? a : b);
    int i = blockIdx.x * blockDim.x + threadIdx.x;
    if (i >= NPAIR) return;
    int e = ridx[i];
    int pos = atomicAdd(&g_cnt[e], 1);
    g_list[e][pos] = i;
    g_coef[i] = rw[i];
    #pragma unroll
    for (int g = 0; g < INTER / GSIZE; g++) g_S1[i][g] = 0.f;  // for GEMM0 atomics
}

// ---------------------------------------------------------------------------
// x -> fp16 + group sums of the ROUNDED values.
// ---------------------------------------------------------------------------
__global__ void k_split(const float* __restrict__ x) {
    int wg   = blockIdx.x * 8 + (threadIdx.x >> 5);
    int lane = threadIdx.x & 31;
    int token = wg >> 4;
    int g     = wg & 15;
    size_t base = (size_t)token * HID + g * GSIZE + lane * 4;
    float4 v = *(const float4*)(x + base);
    __half h0 = __float2half_rn(v.x), h1 = __float2half_rn(v.y);
    __half h2 = __float2half_rn(v.z), h3 = __float2half_rn(v.w);
    ((__half2*)(g_xh + base))[0] = __half2(h0, h1);
    ((__half2*)(g_xh + base))[1] = __half2(h2, h3);
    float sum = __half2float(h0) + __half2float(h1)
              + __half2float(h2) + __half2float(h3);
    #pragma unroll
    for (int o = 16; o; o >>= 1) sum += __shfl_xor_sync(0xFFFFFFFFu, sum, o);
    if (lane == 0) g_S0[token][g] = sum;
}

// ---------------------------------------------------------------------------
// Pipelined fp16 tensor-core dequant GEMM.
// PHASE 0: block = 64 tokens x (64 gate rows [64z..] + 64 up rows [I+64z..]).
//          Fused epilogue computes h = gelu(gate)*up, writes fp16 g_hh and
//          2-contributor-deterministic atomic partial group sums g_S1.
// PHASE 1: block = 64 tokens x 128 rows of HID; stores coef * (h @ dn^T).
// 4-stage cp.async pipeline, unrolled x4, one __syncthreads per chunk.
//   out = sum_g s_g * P'_g + (z_g - 128 s_g) * S_g ; weights (q+128) exact fp16.
// ---------------------------------------------------------------------------
template <int PHASE>
__global__ void __launch_bounds__(256, 2)
mma_gemm(const uint8_t* __restrict__ wpk,
         const float* __restrict__ pa,
         const float* __restrict__ pb)
{
    constexpr int RTOT  = PHASE ? HID   : TWO_I;
    constexpr int INF   = PHASE ? INTER : HID;
    constexpr int NGRP  = INF / GSIZE;
    constexpr int INFH  = INF / 2;
    constexpr int SHIFT = PHASE ? 0 : 1;
    constexpr int NCHUNK = INF / 64;      // 32 or 64, divisible by 4
    constexpr int STG = 13312;            // A 9216 + W 4096

    const int e     = blockIdx.y;
    const int n_tok = g_cnt[e];
    const int t0    = blockIdx.x * 64;    // token-block: fastest dim
    if (t0 >= n_tok) return;
    const int zb   = blockIdx.z;          // weight-row block: slowest dim
    const int tid  = threadIdx.x;
    const int lane = tid & 31;
    const int wid  = tid >> 5;
    const int warp_n = wid;               // 8 warps x 16 rows
    const int trow = lane >> 2;
    const int tcol = (lane & 3) * 2;
    const int bsh  = 8 * (lane & 3);

    const int swp = PHASE ? g_swap_dn : g_swap_gu;
    const float* __restrict__ sc = swp ? pb : pa;
    const float* __restrict__ zp = swp ? pa : pb;
    const int wmode = g_wmode;

    extern __shared__ __align__(16) char sm[];
    float* Ssm   = (float*)(sm + 4 * STG);
    float* Zsm   = Ssm + 64 * NGRP;
    float* Ssc   = Zsm + 128 * NGRP;
    int*   s_pid = (int*)(Ssc + 128 * NGRP);

    const __half* __restrict__ Ag = PHASE ? g_hh : g_xh;
    const float* __restrict__ Sglob = PHASE ? &g_S1[0][0] : &g_S0[0][0];

    if (tid < 64) {
        int slot = t0 + tid;
        s_pid[tid] = (slot < n_tok) ? g_list[e][slot] : -1;
    }
    __syncthreads();

    // weight-row mapping: phase0 = 64 gate rows then 64 up rows; phase1 = 128 rows
    const size_t wbase_g = (size_t)e * RTOT + (PHASE ? (size_t)zb * 128 : (size_t)zb * 64);
    const size_t wbase_u = wbase_g + INTER;   // only used by phase0
    auto wrow_of = [&](int row) -> size_t {
        if (PHASE) return wbase_g + row;
        return (row < 64) ? (wbase_g + row) : (wbase_u + (row - 64));
    };

    // ---- async prefetch of one chunk into stage buffer S ----
    auto prefetch = [&](char* S, int h0) {
        #pragma unroll
        for (int i = 0; i < 2; i++) {
            int idx = tid + i * 256;          // 0..511
            int t   = idx >> 3;
            int seg = idx & 7;
            int p   = s_pid[t];
            int sz  = (p >= 0) ? 16 : 0;
            size_t off = (p >= 0) ? ((size_t)(p >> SHIFT) * INF + h0 + seg * 8) : 0;
            cp16(smaddr(S + t * 144 + seg * 16), Ag + off, sz);
        }
        uint32_t* W = (uint32_t*)(S + 9216);
        if (wmode == 0) {
            int row = tid >> 1;
            int u   = tid & 1;
            const uint8_t* src = wpk + wrow_of(row) * INFH + (h0 >> 1) + u * 16;
            cp16(smaddr(W + row * 8 + ((u << 2) ^ (row & 4))), src, 16);
        } else {
            #pragma unroll
            for (int i = 0; i < 4; i++) {
                int idx = tid + i * 256;
                int row = idx >> 3;
                int wc  = idx & 7;
                size_t eoff = wrow_of(row) * INFH + (h0 >> 1) + wc * 4;
                uint4 v4 = *(const uint4*)((const uint32_t*)wpk + eoff);
                W[row * 8 + (wc ^ (row & 4))] =
                    (v4.x & 0xFFu) | ((v4.y & 0xFFu) << 8)
                  | ((v4.z & 0xFFu) << 16) | ((v4.w & 0xFFu) << 24);
            }
        }
    };

    // prime 3 stages
    prefetch(sm + 0 * STG, 0);
    asm volatile("cp.async.commit_group;");
    prefetch(sm + 1 * STG, 64);
    asm volatile("cp.async.commit_group;");
    prefetch(sm + 2 * STG, 128);
    asm volatile("cp.async.commit_group;");

    // ---- prologue tables ----
    for (int i = tid; i < 64 * NGRP; i += 256) {
        int t = i / NGRP, g = i % NGRP;
        int p = s_pid[t];
        Ssm[i] = (p >= 0) ? Sglob[(size_t)(p >> SHIFT) * NGRP + g] : 0.f;
    }
    for (int i = tid; i < 128 * NGRP; i += 256) {
        int r = i / NGRP, g = i % NGRP;
        size_t idx = wrow_of(r) * NGRP + g;
        float s = sc[idx];
        Zsm[i] = zp[idx] - 128.f * s;
        Ssc[i] = s;
    }

    float cT[4][2][4], cG[4][2][4];
    #pragma unroll
    for (int m = 0; m < 4; m++)
        #pragma unroll
        for (int n = 0; n < 2; n++)
            #pragma unroll
            for (int k = 0; k < 4; k++) { cT[m][n][k] = 0.f; cG[m][n][k] = 0.f; }

    __syncthreads();   // tables ready

    // zero-point term: cT[t][r] = sum_g S[t][g] * z'[r][g]
    #pragma unroll 4
    for (int g = 0; g < NGRP; g++) {
        float sv[4][2];
        #pragma unroll
        for (int m = 0; m < 4; m++) {
            sv[m][0] = Ssm[(m * 16 + trow) * NGRP + g];
            sv[m][1] = Ssm[(m * 16 + trow + 8) * NGRP + g];
        }
        #pragma unroll
        for (int n = 0; n < 2; n++) {
            int rr = warp_n * 16 + n * 8 + tcol;
            float z0 = Zsm[rr * NGRP + g];
            float z1 = Zsm[(rr + 1) * NGRP + g];
            #pragma unroll
            for (int m = 0; m < 4; m++) {
                cT[m][n][0] += sv[m][0] * z0;
                cT[m][n][1] += sv[m][0] * z1;
                cT[m][n][2] += sv[m][1] * z0;
                cT[m][n][3] += sv[m][1] * z1;
            }
        }
    }

    const int lmat = lane >> 3;
    const int lm_off = (((lmat & 1) * 8 + (lane & 7)) * 72 + (lmat >> 1) * 8);

    // ---- main pipelined loop: unrolled x4, static stage pointers ----
    for (int cb = 0; cb < NCHUNK; cb += 4) {
        #pragma unroll
        for (int j = 0; j < 4; j++) {
            const int c = cb + j;
            __syncthreads();
            if (c + 3 < NCHUNK)
                prefetch(sm + ((j + 3) & 3) * STG, (c + 3) * 64);
            asm volatile("cp.async.commit_group;");
            asm volatile("cp.async.wait_group 3;");

            const char* S = sm + j * STG;
            const __half*   A = (const __half*)S;
            const uint32_t* W = (const uint32_t*)(S + 9216);

            #pragma unroll
            for (int ks = 0; ks < 4; ks++) {
                const int kb = ks * 16;
                uint32_t bfrag[2][2];
                #pragma unroll
                for (int n = 0; n < 2; n++) {
                    int rr = warp_n * 16 + n * 8 + trow;
                    uint32_t w0 = W[rr * 8 + ((2 * ks)     ^ (rr & 4))];
                    uint32_t w1 = W[rr * 8 + ((2 * ks + 1) ^ (rr & 4))];
                    uint32_t b0 = (w0 >> bsh) & 0xFFu;
                    uint32_t b1 = (w1 >> bsh) & 0xFFu;
                    bfrag[n][0] = 0x58005800u | ((b0 >> 4) << 3) | ((b0 & 15u) << 19);
                    bfrag[n][1] = 0x58005800u | ((b1 >> 4) << 3) | ((b1 & 15u) << 19);
                }
                #pragma unroll
                for (int m = 0; m < 4; m++) {
                    uint32_t addr = smaddr(A + (m * 16) * 72 + kb + lm_off);
                    uint32_t a0, a1, a2, a3;
                    ldsm4(a0, a1, a2, a3, addr);
                    #pragma unroll
                    for (int n = 0; n < 2; n++)
                        mma_f16(cG[m][n], a0, a1, a2, a3, bfrag[n][0], bfrag[n][1]);
                }
            }

            if (c & 1) {
                int g = c >> 1;
                #pragma unroll
                for (int n = 0; n < 2; n++) {
                    int rr = warp_n * 16 + n * 8 + tcol;
                    float s0 = Ssc[rr * NGRP + g];
                    float s1 = Ssc[(rr + 1) * NGRP + g];
                    #pragma unroll
                    for (int m = 0; m < 4; m++) {
                        cT[m][n][0] += s0 * cG[m][n][0];
                        cT[m][n][1] += s1 * cG[m][n][1];
                        cT[m][n][2] += s0 * cG[m][n][2];
                        cT[m][n][3] += s1 * cG[m][n][3];
                        cG[m][n][0] = 0.f; cG[m][n][1] = 0.f;
                        cG[m][n][2] = 0.f; cG[m][n][3] = 0.f;
                    }
                }
            }
        }
    }

    if (PHASE) {
        // ---- phase1 store: coef * result into g_dn ----
        const int r0 = zb * 128;
        #pragma unroll
        for (int m = 0; m < 4; m++) {
            #pragma unroll
            for (int half = 0; half < 2; half++) {
                int tl = m * 16 + trow + half * 8;
                int p = s_pid[tl];
                if (p < 0) continue;
                float cf = g_coef[p];
                float* Crow = g_dn + (size_t)p * HID + r0 + warp_n * 16;
                #pragma unroll
                for (int n = 0; n < 2; n++) {
                    float2 v;
                    v.x = cT[m][n][half * 2 + 0] * cf;
                    v.y = cT[m][n][half * 2 + 1] * cf;
                    *(float2*)(Crow + n * 8 + tcol) = v;
                }
            }
        }
    } else {
        // ---- phase0 fused epilogue: h = gelu(gate) * up ----
        float*  gs = (float*)sm;                         // [64 j][65] fp32 gate
        __half* hs = (__half*)(sm + 64 * 65 * 4);        // [64 j][66] fp16 h
        float*  ps = (float*)(sm + 64 * 65 * 4 + 64 * 66 * 2);  // [256]
        __syncthreads();    // stage buffers fully consumed
        if (warp_n < 4) {   // gate warps: stash fp32 gate tile
            #pragma unroll
            for (int m = 0; m < 4; m++)
                #pragma unroll
                for (int n = 0; n < 2; n++)
                    #pragma unroll
                    for (int k = 0; k < 4; k++) {
                        int tok = m * 16 + trow + ((k >> 1) ? 8 : 0);
                        int jj  = warp_n * 16 + n * 8 + tcol + (k & 1);
                        gs[jj * 65 + tok] = cT[m][n][k];
                    }
        }
        __syncthreads();
        if (warp_n >= 4) {  // up warps: gelu(gate)*up -> fp16
            #pragma unroll
            for (int m = 0; m < 4; m++)
                #pragma unroll
                for (int n = 0; n < 2; n++)
                    #pragma unroll
                    for (int k = 0; k < 4; k++) {
                        int tok = m * 16 + trow + ((k >> 1) ? 8 : 0);
                        int jj  = (warp_n - 4) * 16 + n * 8 + tcol + (k & 1);
                        float gv = gs[jj * 65 + tok];
                        float uv = cT[m][n][k];
                        float t  = fast_tanh(0.7978845608028654f *
                                             (gv + 0.044715f * gv * gv * gv));
                        float h  = 0.5f * gv * (1.f + t) * uv;
                        hs[jj * 66 + tok] = __float2half_rn(h);
                    }
        }
        __syncthreads();
        // write h (coalesced per token) + partial group sums
        {
            int tok = tid & 63;
            int q   = tid >> 6;            // quarter 0..3
            int p   = s_pid[tok];
            float s = 0.f;
            uint32_t packed[8];
            #pragma unroll
            for (int w = 0; w < 8; w++) {
                __half a = hs[(q * 16 + w * 2 + 0) * 66 + tok];
                __half b = hs[(q * 16 + w * 2 + 1) * 66 + tok];
                s += __half2float(a) + __half2float(b);
                __half2 pr(a, b);
                packed[w] = *reinterpret_cast<uint32_t*>(&pr);
            }
            if (p >= 0) {
                __half* dst = g_hh + (size_t)p * INTER + zb * 64 + q * 16;
                *(uint4*)(dst)     = make_uint4(packed[0], packed[1], packed[2], packed[3]);
                *(uint4*)(dst + 8) = make_uint4(packed[4], packed[5], packed[6], packed[7]);
            }
            ps[tid] = s;
        }
        __syncthreads();
        if (tid < 64) {
            float tot = ps[tid] + ps[tid + 64] + ps[tid + 128] + ps[tid + 192];
            int p = s_pid[tid];
            if (p >= 0) atomicAdd(&g_S1[p][zb >> 1], tot);  // 2 contributors: deterministic
        }
    }
}

// ---------------------------------------------------------------------------
__global__ void k_comb(float* __restrict__ out) {
    int i = blockIdx.x * blockDim.x + threadIdx.x;
    if (i >= TOK * HID) return;
    int t = i >> 11;
    int c = i & (HID - 1);
    out[i] = g_dn[(size_t)(2 * t) * HID + c] + g_dn[(size_t)(2 * t + 1) * HID + c];
}

// ---------------------------------------------------------------------------
extern "C" void kernel_launch(void* const* d_in, const int* in_sizes, int n_in,
                              void* d_out, int out_size)
{
    (void)out_size;
    int ix = 0, igup = 1, igs_a = 2, igs_b = 3, idnp = 4, ids_a = 5, ids_b = 6,
        irt_a = 7, irt_b = 8;

    int gu_pair[2] = {-1, -1}, dn_pair[2] = {-1, -1}, rt_pair[2] = {-1, -1};
    int f_x = -1, f_gup = -1, f_dnp = -1;
    for (int i = 0; i < n_in; i++) {
        long long s = in_sizes[i];
        if      (s == 2097152LL)  f_x = i;
        else if (s == 67108864LL) f_gup = i;
        else if (s == 33554432LL) f_dnp = i;
        else if (s == 1048576LL)  { if (gu_pair[0] < 0) gu_pair[0] = i; else gu_pair[1] = i; }
        else if (s == 524288LL)   { if (dn_pair[0] < 0) dn_pair[0] = i; else dn_pair[1] = i; }
        else if (s == 2048LL)     { if (rt_pair[0] < 0) rt_pair[0] = i; else rt_pair[1] = i; }
    }
    if (f_x >= 0 && f_gup >= 0 && f_dnp >= 0 &&
        gu_pair[1] >= 0 && dn_pair[1] >= 0 && rt_pair[1] >= 0) {
        ix = f_x; igup = f_gup; idnp = f_dnp;
        igs_a = gu_pair[0]; igs_b = gu_pair[1];
        ids_a = dn_pair[0]; ids_b = dn_pair[1];
        irt_a = rt_pair[0]; irt_b = rt_pair[1];
    }

    const float*   x    = (const float*)  d_in[ix];
    const uint8_t* gu_p = (const uint8_t*)d_in[igup];
    const float*   gu_a = (const float*)  d_in[igs_a];
    const float*   gu_b = (const float*)  d_in[igs_b];
    const uint8_t* dn_p = (const uint8_t*)d_in[idnp];
    const float*   dn_a = (const float*)  d_in[ids_a];
    const float*   dn_b = (const float*)  d_in[ids_b];
    const void*    rt_a = d_in[irt_a];
    const void*    rt_b = d_in[irt_b];
    float*         out  = (float*)        d_out;

    // dynamic smem: 4 stages + tables
    const int SMEM0 = 4 * 13312 + (64 + 128 + 128) * (HID / GSIZE) * 4 + 256;   // ~74.0 KB
    const int SMEM1 = 4 * 13312 + (64 + 128 + 128) * (INTER / GSIZE) * 4 + 256; // ~94.5 KB
    cudaFuncSetAttribute(mma_gemm<0>, cudaFuncAttributeMaxDynamicSharedMemorySize, SMEM0);
    cudaFuncSetAttribute(mma_gemm<1>, cudaFuncAttributeMaxDynamicSharedMemorySize, SMEM1);

    k_detect<<<1, 32>>>((const uint32_t*)gu_p, gu_a, dn_a, (const uint32_t*)rt_a);
    k_route<<<NPAIR / 256, 256>>>(rt_a, rt_b);
    k_split<<<TOK * (HID / GSIZE) / 8, 256>>>(x);

    // phase0: z = h-slice (64 gate rows + 64 up rows per block)
    dim3 g0(NPAIR / 64, EXPERTS, INTER / 64);    // (32, 8, 64)
    mma_gemm<0><<<g0, 256, SMEM0>>>(gu_p, gu_a, gu_b);

    dim3 g1(NPAIR / 64, EXPERTS, HID / 128);     // (32, 8, 16)
    mma_gemm<1><<<g1, 256, SMEM1>>>(dn_p, dn_a, dn_b);

    k_comb<<<(TOK * HID) / 256, 256>>>(out);
}

// round 15
// speedup vs baseline: 1.0297x; 1.0297x over previous
#include <cuda_runtime.h>
#include <cuda_fp16.h>
#include <cstdint>

#define EXPERTS 8
#define HID     2048
#define INTER   4096
#define TWO_I   8192
#define TOK     1024
#define NPAIR   2048
#define GSIZE   128

// ---------------------------------------------------------------------------
// Scratch (static __device__ globals)
// ---------------------------------------------------------------------------
__device__ float  g_gu[(size_t)NPAIR * TWO_I];
__device__ __half g_hh[(size_t)NPAIR * INTER];   // h rounded to fp16
__device__ __half g_xh[(size_t)TOK * HID];       // x rounded to fp16
__device__ float  g_S0[TOK][HID / GSIZE];        // group sums of fp16(x)
__device__ float  g_S1[NPAIR][INTER / GSIZE];    // group sums of fp16(h)
__device__ int    g_cnt[EXPERTS];
__device__ int    g_list[EXPERTS][NPAIR];
__device__ float  g_coef[NPAIR];

__device__ int g_wmode, g_swap_gu, g_swap_dn, g_swap_rt;

// ---------------------------------------------------------------------------
// helpers
// ---------------------------------------------------------------------------
__device__ __forceinline__ uint32_t smaddr(const void* p) {
    return (uint32_t)__cvta_generic_to_shared(p);
}
__device__ __forceinline__ void cp16(uint32_t dst, const void* src, int srcbytes) {
    asm volatile("cp.async.cg.shared.global [%0], [%1], 16, %2;"
                 :: "r"(dst), "l"(src), "r"(srcbytes));
}
__device__ __forceinline__ void ldsm4(uint32_t& a0, uint32_t& a1,
                                      uint32_t& a2, uint32_t& a3, uint32_t addr) {
    asm volatile("ldmatrix.sync.aligned.m8n8.x4.shared.b16 {%0,%1,%2,%3}, [%4];"
                 : "=r"(a0), "=r"(a1), "=r"(a2), "=r"(a3) : "r"(addr));
}
__device__ __forceinline__ void mma_f16(float c[4],
    uint32_t a0, uint32_t a1, uint32_t a2, uint32_t a3, uint32_t b0, uint32_t b1)
{
    asm("mma.sync.aligned.m16n8k16.row.col.f32.f16.f16.f32 "
        "{%0,%1,%2,%3}, {%4,%5,%6,%7}, {%8,%9}, {%0,%1,%2,%3};\n"
        : "+f"(c[0]), "+f"(c[1]), "+f"(c[2]), "+f"(c[3])
        : "r"(a0), "r"(a1), "r"(a2), "r"(a3), "r"(b0), "r"(b1));
}

// ---------------------------------------------------------------------------
// Setup kernels
// ---------------------------------------------------------------------------
__global__ void k_detect(const uint32_t* __restrict__ gup,
                         const float* __restrict__ gus_a,
                         const float* __restrict__ dns_a,
                         const uint32_t* __restrict__ rt_a)
{
    if (threadIdx.x < EXPERTS) g_cnt[threadIdx.x] = 0;
    if (threadIdx.x != 0) return;
    int widened = 1;
    for (int i = 0; i < 16; i++)
        if (gup[i] & 0xFFFFFF00u) widened = 0;
    g_wmode = widened;
    int neg = 0;
    for (int i = 0; i < 9; i++) neg += (gus_a[i] < 0.f) ? 1 : 0;
    g_swap_gu = (neg > 4) ? 1 : 0;
    neg = 0;
    for (int i = 0; i < 9; i++) neg += (dns_a[i] < 0.f) ? 1 : 0;
    g_swap_dn = (neg > 4) ? 1 : 0;
    int small = 1;
    for (int i = 0; i < 16; i++)
        if (rt_a[i] >= 256u) small = 0;
    g_swap_rt = small ? 0 : 1;
}

__global__ void k_route(const void* __restrict__ a, const void* __restrict__ b) {
    const int*   ridx = (const int*)  (g_swap_rt ? b : a);
    const float* rw   = (const float*)(g_swap_rt ? a : b);
    int i = blockIdx.x * blockDim.x + threadIdx.x;
    if (i >= NPAIR) return;
    int e = ridx[i];
    int pos = atomicAdd(&g_cnt[e], 1);
    g_list[e][pos] = i;
    g_coef[i] = rw[i];
}

// ---------------------------------------------------------------------------
// x -> fp16 + group sums of the ROUNDED values; also zero `out` (same index
// space: one warp covers 128 contiguous floats of out).
// ---------------------------------------------------------------------------
__global__ void k_split(const float* __restrict__ x, float* __restrict__ out) {
    int wg   = blockIdx.x * 8 + (threadIdx.x >> 5);
    int lane = threadIdx.x & 31;
    int token = wg >> 4;
    int g     = wg & 15;
    size_t base = (size_t)token * HID + g * GSIZE + lane * 4;
    float4 v = *(const float4*)(x + base);
    __half h0 = __float2half_rn(v.x), h1 = __float2half_rn(v.y);
    __half h2 = __float2half_rn(v.z), h3 = __float2half_rn(v.w);
    ((__half2*)(g_xh + base))[0] = __half2(h0, h1);
    ((__half2*)(g_xh + base))[1] = __half2(h2, h3);
    *(float4*)(out + base) = make_float4(0.f, 0.f, 0.f, 0.f);
    float sum = __half2float(h0) + __half2float(h1)
              + __half2float(h2) + __half2float(h3);
    #pragma unroll
    for (int o = 16; o; o >>= 1) sum += __shfl_xor_sync(0xFFFFFFFFu, sum, o);
    if (lane == 0) g_S0[token][g] = sum;
}

__device__ __forceinline__ float fast_tanh(float x) {
    float e, inv;
    float ax = fabsf(x) * 2.8853900817779268f;
    asm("ex2.approx.f32 %0, %1;" : "=f"(e) : "f"(ax));
    asm("rcp.approx.f32 %0, %1;" : "=f"(inv) : "f"(e + 1.f));
    return copysignf(1.f - 2.f * inv, x);
}

__global__ void k_gelu() {
    int wg   = blockIdx.x * 8 + (threadIdx.x >> 5);
    int lane = threadIdx.x & 31;
    int pid = wg >> 5;
    int g   = wg & 31;
    size_t base = (size_t)pid * INTER + g * GSIZE + lane * 4;
    size_t gub  = (size_t)pid * TWO_I + g * GSIZE + lane * 4;
    float4 gg = *(const float4*)(g_gu + gub);
    float4 uu = *(const float4*)(g_gu + gub + INTER);
    float gv[4] = {gg.x, gg.y, gg.z, gg.w};
    float uv[4] = {uu.x, uu.y, uu.z, uu.w};
    __half hh[4];
    float sum = 0.f;
    #pragma unroll
    for (int i = 0; i < 4; i++) {
        float t = fast_tanh(0.7978845608028654f * (gv[i] + 0.044715f * gv[i] * gv[i] * gv[i]));
        float h = 0.5f * gv[i] * (1.f + t) * uv[i];
        hh[i] = __float2half_rn(h);
        sum += __half2float(hh[i]);
    }
    ((__half2*)(g_hh + base))[0] = __half2(hh[0], hh[1]);
    ((__half2*)(g_hh + base))[1] = __half2(hh[2], hh[3]);
    #pragma unroll
    for (int o = 16; o; o >>= 1) sum += __shfl_xor_sync(0xFFFFFFFFu, sum, o);
    if (lane == 0) g_S1[pid][g] = sum;
}

// ---------------------------------------------------------------------------
// Pipelined fp16 tensor-core dequant GEMM (r13 structure).
// Block: 64 tokens x 128 rows x 64-k chunks, 8 warps, warp tile 64 tok x 16 rows.
// 4-stage cp.async pipeline, unrolled x4 (static stage pointers), 1 barrier/chunk.
// GRID: x = token-block (fastest), y = expert, z = weight-row-block (slowest).
// PHASE 0 stores fp32 gate|up to g_gu. PHASE 1 accumulates coef*val directly
// into `out` via atomicAdd (exactly 2 contributors per element: deterministic).
//   out = sum_g s_g * P'_g + (z_g - 128 s_g) * S_g ; weights (q+128) exact fp16.
// ---------------------------------------------------------------------------
template <int PHASE>
__global__ void __launch_bounds__(256, 2)
mma_gemm(const uint8_t* __restrict__ wpk,
         const float* __restrict__ pa,
         const float* __restrict__ pb,
         float* __restrict__ outp)
{
    constexpr int RTOT  = PHASE ? HID   : TWO_I;
    constexpr int INF   = PHASE ? INTER : HID;
    constexpr int NGRP  = INF / GSIZE;
    constexpr int INFH  = INF / 2;
    constexpr int SHIFT = PHASE ? 0 : 1;
    constexpr int NCHUNK = INF / 64;      // 32 or 64, divisible by 4
    constexpr int STG = 13312;            // A 9216 + W 4096

    const int e     = blockIdx.y;
    const int n_tok = g_cnt[e];
    const int t0    = blockIdx.x * 64;    // token-block: fastest dim
    if (t0 >= n_tok) return;
    const int r0   = blockIdx.z * 128;    // weight-row-block: slowest dim
    const int tid  = threadIdx.x;
    const int lane = tid & 31;
    const int wid  = tid >> 5;
    const int warp_n = wid;               // 8 warps x 16 rows
    const int trow = lane >> 2;
    const int tcol = (lane & 3) * 2;
    const int bsh  = 8 * (lane & 3);

    const int swp = PHASE ? g_swap_dn : g_swap_gu;
    const float* __restrict__ sc = swp ? pb : pa;
    const float* __restrict__ zp = swp ? pa : pb;
    const int wmode = g_wmode;

    extern __shared__ __align__(16) char sm[];
    float* Ssm   = (float*)(sm + 4 * STG);
    float* Zsm   = Ssm + 64 * NGRP;
    float* Ssc   = Zsm + 128 * NGRP;
    int*   s_pid = (int*)(Ssc + 128 * NGRP);

    const __half* __restrict__ Ag = PHASE ? g_hh : g_xh;
    const float* __restrict__ Sglob = PHASE ? &g_S1[0][0] : &g_S0[0][0];

    if (tid < 64) {
        int slot = t0 + tid;
        s_pid[tid] = (slot < n_tok) ? g_list[e][slot] : -1;
    }
    __syncthreads();

    const size_t wrowbase = (size_t)e * RTOT + r0;

    // ---- async prefetch of one chunk into stage buffer S ----
    auto prefetch = [&](char* S, int h0) {
        #pragma unroll
        for (int i = 0; i < 2; i++) {
            int idx = tid + i * 256;          // 0..511
            int t   = idx >> 3;
            int seg = idx & 7;
            int p   = s_pid[t];
            int sz  = (p >= 0) ? 16 : 0;
            size_t off = (p >= 0) ? ((size_t)(p >> SHIFT) * INF + h0 + seg * 8) : 0;
            cp16(smaddr(S + t * 144 + seg * 16), Ag + off, sz);
        }
        uint32_t* W = (uint32_t*)(S + 9216);
        if (wmode == 0) {
            int row = tid >> 1;
            int u   = tid & 1;
            const uint8_t* src = wpk + (wrowbase + row) * INFH + (h0 >> 1) + u * 16;
            cp16(smaddr(W + row * 8 + ((u << 2) ^ (row & 4))), src, 16);
        } else {
            #pragma unroll
            for (int i = 0; i < 4; i++) {
                int idx = tid + i * 256;
                int row = idx >> 3;
                int wc  = idx & 7;
                size_t eoff = (wrowbase + row) * INFH + (h0 >> 1) + wc * 4;
                uint4 v4 = *(const uint4*)((const uint32_t*)wpk + eoff);
                W[row * 8 + (wc ^ (row & 4))] =
                    (v4.x & 0xFFu) | ((v4.y & 0xFFu) << 8)
                  | ((v4.z & 0xFFu) << 16) | ((v4.w & 0xFFu) << 24);
            }
        }
    };

    // prime 3 stages
    prefetch(sm + 0 * STG, 0);
    asm volatile("cp.async.commit_group;");
    prefetch(sm + 1 * STG, 64);
    asm volatile("cp.async.commit_group;");
    prefetch(sm + 2 * STG, 128);
    asm volatile("cp.async.commit_group;");

    // ---- prologue tables ----
    for (int i = tid; i < 64 * NGRP; i += 256) {
        int t = i / NGRP, g = i % NGRP;
        int p = s_pid[t];
        Ssm[i] = (p >= 0) ? Sglob[(size_t)(p >> SHIFT) * NGRP + g] : 0.f;
    }
    for (int i = tid; i < 128 * NGRP; i += 256) {
        int r = i / NGRP, g = i % NGRP;
        size_t idx = (wrowbase + r) * NGRP + g;
        float s = sc[idx];
        Zsm[i] = zp[idx] - 128.f * s;
        Ssc[i] = s;
    }

    float cT[4][2][4], cG[4][2][4];
    #pragma unroll
    for (int m = 0; m < 4; m++)
        #pragma unroll
        for (int n = 0; n < 2; n++)
            #pragma unroll
            for (int k = 0; k < 4; k++) { cT[m][n][k] = 0.f; cG[m][n][k] = 0.f; }

    __syncthreads();   // tables ready

    // zero-point term: cT[t][r] = sum_g S[t][g] * z'[r][g]
    #pragma unroll 4
    for (int g = 0; g < NGRP; g++) {
        float sv[4][2];
        #pragma unroll
        for (int m = 0; m < 4; m++) {
            sv[m][0] = Ssm[(m * 16 + trow) * NGRP + g];
            sv[m][1] = Ssm[(m * 16 + trow + 8) * NGRP + g];
        }
        #pragma unroll
        for (int n = 0; n < 2; n++) {
            int rr = warp_n * 16 + n * 8 + tcol;
            float z0 = Zsm[rr * NGRP + g];
            float z1 = Zsm[(rr + 1) * NGRP + g];
            #pragma unroll
            for (int m = 0; m < 4; m++) {
                cT[m][n][0] += sv[m][0] * z0;
                cT[m][n][1] += sv[m][0] * z1;
                cT[m][n][2] += sv[m][1] * z0;
                cT[m][n][3] += sv[m][1] * z1;
            }
        }
    }

    const int lmat = lane >> 3;
    const int lm_off = (((lmat & 1) * 8 + (lane & 7)) * 72 + (lmat >> 1) * 8);

    // ---- main pipelined loop: unrolled x4, static stage pointers ----
    for (int cb = 0; cb < NCHUNK; cb += 4) {
        #pragma unroll
        for (int j = 0; j < 4; j++) {
            const int c = cb + j;
            __syncthreads();   // all warps consumed stage (j+3)&3 (chunk c-1)
            if (c + 3 < NCHUNK)
                prefetch(sm + ((j + 3) & 3) * STG, (c + 3) * 64);
            asm volatile("cp.async.commit_group;");  // always (empty ok)
            asm volatile("cp.async.wait_group 3;");  // chunk c's copies done

            const char* S = sm + j * STG;
            const __half*   A = (const __half*)S;
            const uint32_t* W = (const uint32_t*)(S + 9216);

            #pragma unroll
            for (int ks = 0; ks < 4; ks++) {
                const int kb = ks * 16;
                uint32_t bfrag[2][2];
                #pragma unroll
                for (int n = 0; n < 2; n++) {
                    int rr = warp_n * 16 + n * 8 + trow;
                    uint32_t w0 = W[rr * 8 + ((2 * ks)     ^ (rr & 4))];
                    uint32_t w1 = W[rr * 8 + ((2 * ks + 1) ^ (rr & 4))];
                    uint32_t b0 = (w0 >> bsh) & 0xFFu;
                    uint32_t b1 = (w1 >> bsh) & 0xFFu;
                    // fp16(128+q) = 0x5800 | (q<<3); even = high nib, odd = low
                    bfrag[n][0] = 0x58005800u | ((b0 >> 4) << 3) | ((b0 & 15u) << 19);
                    bfrag[n][1] = 0x58005800u | ((b1 >> 4) << 3) | ((b1 & 15u) << 19);
                }
                #pragma unroll
                for (int m = 0; m < 4; m++) {
                    uint32_t addr = smaddr(A + (m * 16) * 72 + kb + lm_off);
                    uint32_t a0, a1, a2, a3;
                    ldsm4(a0, a1, a2, a3, addr);
                    #pragma unroll
                    for (int n = 0; n < 2; n++)
                        mma_f16(cG[m][n], a0, a1, a2, a3, bfrag[n][0], bfrag[n][1]);
                }
            }

            // group boundary (every 128 k = 2 chunks): fold s_g * P'_g
            if (c & 1) {
                int g = c >> 1;
                #pragma unroll
                for (int n = 0; n < 2; n++) {
                    int rr = warp_n * 16 + n * 8 + tcol;
                    float s0 = Ssc[rr * NGRP + g];
                    float s1 = Ssc[(rr + 1) * NGRP + g];
                    #pragma unroll
                    for (int m = 0; m < 4; m++) {
                        cT[m][n][0] += s0 * cG[m][n][0];
                        cT[m][n][1] += s1 * cG[m][n][1];
                        cT[m][n][2] += s0 * cG[m][n][2];
                        cT[m][n][3] += s1 * cG[m][n][3];
                        cG[m][n][0] = 0.f; cG[m][n][1] = 0.f;
                        cG[m][n][2] = 0.f; cG[m][n][3] = 0.f;
                    }
                }
            }
        }
    }

    // ---- store ----
    #pragma unroll
    for (int m = 0; m < 4; m++) {
        #pragma unroll
        for (int half = 0; half < 2; half++) {
            int tl = m * 16 + trow + half * 8;
            int p = s_pid[tl];
            if (p < 0) continue;
            if (PHASE) {
                // accumulate coef * val directly into out[token][col]
                // exactly 2 contributors per element (K=2) -> deterministic
                float cf = g_coef[p];
                float* Orow = outp + (size_t)(p >> 1) * HID + r0 + warp_n * 16;
                #pragma unroll
                for (int n = 0; n < 2; n++) {
                    atomicAdd(Orow + n * 8 + tcol,     cT[m][n][half * 2 + 0] * cf);
                    atomicAdd(Orow + n * 8 + tcol + 1, cT[m][n][half * 2 + 1] * cf);
                }
            } else {
                float* Crow = g_gu + (size_t)p * TWO_I + r0 + warp_n * 16;
                #pragma unroll
                for (int n = 0; n < 2; n++) {
                    float2 v;
                    v.x = cT[m][n][half * 2 + 0];
                    v.y = cT[m][n][half * 2 + 1];
                    *(float2*)(Crow + n * 8 + tcol) = v;
                }
            }
        }
    }
}

// ---------------------------------------------------------------------------
extern "C" void kernel_launch(void* const* d_in, const int* in_sizes, int n_in,
                              void* d_out, int out_size)
{
    (void)out_size;
    int ix = 0, igup = 1, igs_a = 2, igs_b = 3, idnp = 4, ids_a = 5, ids_b = 6,
        irt_a = 7, irt_b = 8;

    int gu_pair[2] = {-1, -1}, dn_pair[2] = {-1, -1}, rt_pair[2] = {-1, -1};
    int f_x = -1, f_gup = -1, f_dnp = -1;
    for (int i = 0; i < n_in; i++) {
        long long s = in_sizes[i];
        if      (s == 2097152LL)  f_x = i;
        else if (s == 67108864LL) f_gup = i;
        else if (s == 33554432LL) f_dnp = i;
        else if (s == 1048576LL)  { if (gu_pair[0] < 0) gu_pair[0] = i; else gu_pair[1] = i; }
        else if (s == 524288LL)   { if (dn_pair[0] < 0) dn_pair[0] = i; else dn_pair[1] = i; }
        else if (s == 2048LL)     { if (rt_pair[0] < 0) rt_pair[0] = i; else rt_pair[1] = i; }
    }
    if (f_x >= 0 && f_gup >= 0 && f_dnp >= 0 &&
        gu_pair[1] >= 0 && dn_pair[1] >= 0 && rt_pair[1] >= 0) {
        ix = f_x; igup = f_gup; idnp = f_dnp;
        igs_a = gu_pair[0]; igs_b = gu_pair[1];
        ids_a = dn_pair[0]; ids_b = dn_pair[1];
        irt_a = rt_pair[0]; irt_b = rt_pair[1];
    }

    const float*   x    = (const float*)  d_in[ix];
    const uint8_t* gu_p = (const uint8_t*)d_in[igup];
    const float*   gu_a = (const float*)  d_in[igs_a];
    const float*   gu_b = (const float*)  d_in[igs_b];
    const uint8_t* dn_p = (const uint8_t*)d_in[idnp];
    const float*   dn_a = (const float*)  d_in[ids_a];
    const float*   dn_b = (const float*)  d_in[ids_b];
    const void*    rt_a = d_in[irt_a];
    const void*    rt_b = d_in[irt_b];
    float*         out  = (float*)        d_out;

    // dynamic smem: 4 stages + tables
    const int SMEM0 = 4 * 13312 + (64 + 128 + 128) * (HID / GSIZE) * 4 + 256;   // ~74.0 KB
    const int SMEM1 = 4 * 13312 + (64 + 128 + 128) * (INTER / GSIZE) * 4 + 256; // ~94.5 KB
    cudaFuncSetAttribute(mma_gemm<0>, cudaFuncAttributeMaxDynamicSharedMemorySize, SMEM0);
    cudaFuncSetAttribute(mma_gemm<1>, cudaFuncAttributeMaxDynamicSharedMemorySize, SMEM1);

    k_detect<<<1, 32>>>((const uint32_t*)gu_p, gu_a, dn_a, (const uint32_t*)rt_a);
    k_route<<<NPAIR / 256, 256>>>(rt_a, rt_b);
    k_split<<<TOK * (HID / GSIZE) / 8, 256>>>(x, out);

    // grid: (token_block fastest, expert, row_block slowest)
    dim3 g0(NPAIR / 64, EXPERTS, TWO_I / 128);   // (32, 8, 64)
    mma_gemm<0><<<g0, 256, SMEM0>>>(gu_p, gu_a, gu_b, out);

    k_gelu<<<NPAIR * (INTER / GSIZE) / 8, 256>>>();

    dim3 g1(NPAIR / 64, EXPERTS, HID / 128);     // (32, 8, 16)
    mma_gemm<1><<<g1, 256, SMEM1>>>(dn_p, dn_a, dn_b, out);
}

// round 16
// speedup vs baseline: 1.1066x; 1.0747x over previous
#include <cuda_runtime.h>
#include <cuda_fp16.h>
#include <cstdint>

#define EXPERTS 8
#define HID     2048
#define INTER   4096
#define TWO_I   8192
#define TOK     1024
#define NPAIR   2048
#define GSIZE   128

// ---------------------------------------------------------------------------
// Scratch (static __device__ globals)
// ---------------------------------------------------------------------------
__device__ float  g_gu[(size_t)NPAIR * TWO_I];
__device__ __half g_hh[(size_t)NPAIR * INTER];   // h rounded to fp16
__device__ __half g_xh[(size_t)TOK * HID];       // x rounded to fp16
__device__ float  g_S0[TOK][HID / GSIZE];        // group sums of fp16(x)
__device__ float  g_S1[NPAIR][INTER / GSIZE];    // group sums of fp16(h)
__device__ int    g_cnt[EXPERTS];
__device__ int    g_list[EXPERTS][NPAIR];
__device__ float  g_coef[NPAIR];

__device__ int g_wmode, g_swap_gu, g_swap_dn, g_swap_rt;

// ---------------------------------------------------------------------------
// helpers
// ---------------------------------------------------------------------------
__device__ __forceinline__ uint32_t smaddr(const void* p) {
    return (uint32_t)__cvta_generic_to_shared(p);
}
__device__ __forceinline__ void cp16(uint32_t dst, const void* src, int srcbytes) {
    asm volatile("cp.async.cg.shared.global [%0], [%1], 16, %2;"
                 :: "r"(dst), "l"(src), "r"(srcbytes));
}
__device__ __forceinline__ void ldsm4(uint32_t& a0, uint32_t& a1,
                                      uint32_t& a2, uint32_t& a3, uint32_t addr) {
    asm volatile("ldmatrix.sync.aligned.m8n8.x4.shared.b16 {%0,%1,%2,%3}, [%4];"
                 : "=r"(a0), "=r"(a1), "=r"(a2), "=r"(a3) : "r"(addr));
}
__device__ __forceinline__ void mma_f16(float c[4],
    uint32_t a0, uint32_t a1, uint32_t a2, uint32_t a3, uint32_t b0, uint32_t b1)
{
    asm("mma.sync.aligned.m16n8k16.row.col.f32.f16.f16.f32 "
        "{%0,%1,%2,%3}, {%4,%5,%6,%7}, {%8,%9}, {%0,%1,%2,%3};\n"
        : "+f"(c[0]), "+f"(c[1]), "+f"(c[2]), "+f"(c[3])
        : "r"(a0), "r"(a1), "r"(a2), "r"(a3), "r"(b0), "r"(b1));
}

// ---------------------------------------------------------------------------
// Setup kernels
// ---------------------------------------------------------------------------
__global__ void k_detect(const uint32_t* __restrict__ gup,
                         const float* __restrict__ gus_a,
                         const float* __restrict__ dns_a,
                         const uint32_t* __restrict__ rt_a)
{
    if (threadIdx.x < EXPERTS) g_cnt[threadIdx.x] = 0;
    if (threadIdx.x != 0) return;
    int widened = 1;
    for (int i = 0; i < 16; i++)
        if (gup[i] & 0xFFFFFF00u) widened = 0;
    g_wmode = widened;
    int neg = 0;
    for (int i = 0; i < 9; i++) neg += (gus_a[i] < 0.f) ? 1 : 0;
    g_swap_gu = (neg > 4) ? 1 : 0;
    neg = 0;
    for (int i = 0; i < 9; i++) neg += (dns_a[i] < 0.f) ? 1 : 0;
    g_swap_dn = (neg > 4) ? 1 : 0;
    int small = 1;
    for (int i = 0; i < 16; i++)
        if (rt_a[i] >= 256u) small = 0;
    g_swap_rt = small ? 0 : 1;
}

__global__ void k_route(const void* __restrict__ a, const void* __restrict__ b) {
    const int*   ridx = (const int*)  (g_swap_rt ? b : a);
    const float* rw   = (const float*)(g_swap_rt ? a : b);
    int i = blockIdx.x * blockDim.x + threadIdx.x;
    if (i >= NPAIR) return;
    int e = ridx[i];
    int pos = atomicAdd(&g_cnt[e], 1);
    g_list[e][pos] = i;
    g_coef[i] = rw[i];
}

// ---------------------------------------------------------------------------
// x -> fp16 + group sums of the ROUNDED values; also zero `out`.
// ---------------------------------------------------------------------------
__global__ void k_split(const float* __restrict__ x, float* __restrict__ out) {
    int wg   = blockIdx.x * 8 + (threadIdx.x >> 5);
    int lane = threadIdx.x & 31;
    int token = wg >> 4;
    int g     = wg & 15;
    size_t base = (size_t)token * HID + g * GSIZE + lane * 4;
    float4 v = *(const float4*)(x + base);
    __half h0 = __float2half_rn(v.x), h1 = __float2half_rn(v.y);
    __half h2 = __float2half_rn(v.z), h3 = __float2half_rn(v.w);
    ((__half2*)(g_xh + base))[0] = __half2(h0, h1);
    ((__half2*)(g_xh + base))[1] = __half2(h2, h3);
    *(float4*)(out + base) = make_float4(0.f, 0.f, 0.f, 0.f);
    float sum = __half2float(h0) + __half2float(h1)
              + __half2float(h2) + __half2float(h3);
    #pragma unroll
    for (int o = 16; o; o >>= 1) sum += __shfl_xor_sync(0xFFFFFFFFu, sum, o);
    if (lane == 0) g_S0[token][g] = sum;
}

__device__ __forceinline__ float fast_tanh(float x) {
    float e, inv;
    float ax = fabsf(x) * 2.8853900817779268f;
    asm("ex2.approx.f32 %0, %1;" : "=f"(e) : "f"(ax));
    asm("rcp.approx.f32 %0, %1;" : "=f"(inv) : "f"(e + 1.f));
    return copysignf(1.f - 2.f * inv, x);
}

__global__ void k_gelu() {
    int wg   = blockIdx.x * 8 + (threadIdx.x >> 5);
    int lane = threadIdx.x & 31;
    int pid = wg >> 5;
    int g   = wg & 31;
    size_t base = (size_t)pid * INTER + g * GSIZE + lane * 4;
    size_t gub  = (size_t)pid * TWO_I + g * GSIZE + lane * 4;
    float4 gg = *(const float4*)(g_gu + gub);
    float4 uu = *(const float4*)(g_gu + gub + INTER);
    float gv[4] = {gg.x, gg.y, gg.z, gg.w};
    float uv[4] = {uu.x, uu.y, uu.z, uu.w};
    __half hh[4];
    float sum = 0.f;
    #pragma unroll
    for (int i = 0; i < 4; i++) {
        float t = fast_tanh(0.7978845608028654f * (gv[i] + 0.044715f * gv[i] * gv[i] * gv[i]));
        float h = 0.5f * gv[i] * (1.f + t) * uv[i];
        hh[i] = __float2half_rn(h);
        sum += __half2float(hh[i]);
    }
    ((__half2*)(g_hh + base))[0] = __half2(hh[0], hh[1]);
    ((__half2*)(g_hh + base))[1] = __half2(hh[2], hh[3]);
    #pragma unroll
    for (int o = 16; o; o >>= 1) sum += __shfl_xor_sync(0xFFFFFFFFu, sum, o);
    if (lane == 0) g_S1[pid][g] = sum;
}

// ---------------------------------------------------------------------------
// Pipelined fp16 tensor-core dequant GEMM.
// Block: 64 tokens x 128 rows x 64-k chunks, 8 warps, warp tile 64 tok x 16 rows.
// 4-stage cp.async pipeline, unrolled x4 (static stage pointers), 1 barrier/chunk.
// Strength-reduced prefetch (hoisted pointers); weights (q+1024) exact fp16 via
// PRMT+magic; zero-point term uses z' = z - 1024 s.
// PHASE 0 stores fp32 gate|up to g_gu. PHASE 1 accumulates coef*val into `out`
// via atomicAdd (exactly 2 contributors per element: deterministic).
// ---------------------------------------------------------------------------
template <int PHASE>
__global__ void __launch_bounds__(256, 2)
mma_gemm(const uint8_t* __restrict__ wpk,
         const float* __restrict__ pa,
         const float* __restrict__ pb,
         float* __restrict__ outp)
{
    constexpr int RTOT  = PHASE ? HID   : TWO_I;
    constexpr int INF   = PHASE ? INTER : HID;
    constexpr int NGRP  = INF / GSIZE;
    constexpr int INFH  = INF / 2;        // packed units per row (u32 in widened view)
    constexpr int SHIFT = PHASE ? 0 : 1;
    constexpr int NCHUNK = INF / 64;
    constexpr int STG = 13312;            // A 9216 + W 4096

    const int e     = blockIdx.y;
    const int n_tok = g_cnt[e];
    const int t0    = blockIdx.x * 64;    // token-block: fastest dim
    if (t0 >= n_tok) return;
    const int r0   = blockIdx.z * 128;    // weight-row-block: slowest dim
    const int tid  = threadIdx.x;
    const int lane = tid & 31;
    const int wid  = tid >> 5;
    const int warp_n = wid;               // 8 warps x 16 rows
    const int trow = lane >> 2;
    const int tcol = (lane & 3) * 2;
    const uint32_t psel = 0x4440u | (lane & 3);   // PRMT: isolate byte (lane&3)

    const int swp = PHASE ? g_swap_dn : g_swap_gu;
    const float* __restrict__ sc = swp ? pb : pa;
    const float* __restrict__ zp = swp ? pa : pb;
    const int wmode = g_wmode;

    extern __shared__ __align__(16) char sm[];
    float* Ssm   = (float*)(sm + 4 * STG);
    float* Zsm   = Ssm + 64 * NGRP;
    float* Ssc   = Zsm + 128 * NGRP;
    int*   s_pid = (int*)(Ssc + 128 * NGRP);

    const __half* __restrict__ Ag = PHASE ? g_hh : g_xh;
    const float* __restrict__ Sglob = PHASE ? &g_S1[0][0] : &g_S0[0][0];

    if (tid < 64) {
        int slot = t0 + tid;
        s_pid[tid] = (slot < n_tok) ? g_list[e][slot] : -1;
    }
    __syncthreads();

    const size_t wrowbase = (size_t)e * RTOT + r0;

    // ---- hoisted prefetch state (per-thread invariants) ----
    // A side: two token slices per thread
    const int tA0 = tid >> 3, tA1 = tA0 + 32;
    const int segA = (tid & 7) * 8;                 // fp16 offset within chunk
    const int pA0 = s_pid[tA0], pA1 = s_pid[tA1];
    const __half* asrc0 = Ag + ((pA0 >= 0) ? ((size_t)(pA0 >> SHIFT) * INF + segA) : 0);
    const __half* asrc1 = Ag + ((pA1 >= 0) ? ((size_t)(pA1 >> SHIFT) * INF + segA) : 0);
    const int asz0 = (pA0 >= 0) ? 16 : 0;
    const int asz1 = (pA1 >= 0) ? 16 : 0;
    const uint32_t adst0 = (uint32_t)(tA0 * 144 + (tid & 7) * 16);
    const uint32_t adst1 = (uint32_t)(tA1 * 144 + (tid & 7) * 16);
    // W side (widened layout): base u32 offset + static per-i deltas
    const int rowW = tid >> 3;                      // 0..31 (+ i*32)
    const int wcW  = tid & 7;
    const uint32_t we0 = (uint32_t)((wrowbase + rowW) * INFH) + wcW * 4;
    const uint32_t wdst0 = 9216u + (uint32_t)((rowW * 8 + (wcW ^ (rowW & 4))) * 4);
    const uint32_t* __restrict__ wsrc32 = (const uint32_t*)wpk;

    // ---- async prefetch of one chunk into stage buffer S ----
    auto prefetch = [&](char* S, int h0) {
        cp16(smaddr(S) + adst0, asrc0 + h0, asz0);
        cp16(smaddr(S) + adst1, asrc1 + h0, asz1);
        if (wmode == 0) {
            uint32_t* W = (uint32_t*)(S + 9216);
            int row = tid >> 1;
            int u   = tid & 1;
            const uint8_t* src = wpk + (wrowbase + row) * INFH + (h0 >> 1) + u * 16;
            cp16(smaddr(W + row * 8 + ((u << 2) ^ (row & 4))), src, 16);
        } else {
            const uint32_t* src = wsrc32 + we0 + (h0 >> 1);
            #pragma unroll
            for (int i = 0; i < 4; i++) {
                uint4 v4 = *(const uint4*)(src + (uint32_t)i * (32u * INFH));
                uint32_t b01 = __byte_perm(v4.x, v4.y, 0x0040);
                uint32_t b23 = __byte_perm(v4.z, v4.w, 0x0040);
                *(uint32_t*)(S + wdst0 + i * 1024) = __byte_perm(b01, b23, 0x5410);
            }
        }
    };

    // prime 3 stages
    prefetch(sm + 0 * STG, 0);
    asm volatile("cp.async.commit_group;");
    prefetch(sm + 1 * STG, 64);
    asm volatile("cp.async.commit_group;");
    prefetch(sm + 2 * STG, 128);
    asm volatile("cp.async.commit_group;");

    // ---- prologue tables ----
    for (int i = tid; i < 64 * NGRP; i += 256) {
        int t = i / NGRP, g = i % NGRP;
        int p = s_pid[t];
        Ssm[i] = (p >= 0) ? Sglob[(size_t)(p >> SHIFT) * NGRP + g] : 0.f;
    }
    for (int i = tid; i < 128 * NGRP; i += 256) {
        int r = i / NGRP, g = i % NGRP;
        size_t idx = (wrowbase + r) * NGRP + g;
        float s = sc[idx];
        Zsm[i] = zp[idx] - 1024.f * s;     // weights are (q + 1024)
        Ssc[i] = s;
    }

    float cT[4][2][4], cG[4][2][4];
    #pragma unroll
    for (int m = 0; m < 4; m++)
        #pragma unroll
        for (int n = 0; n < 2; n++)
            #pragma unroll
            for (int k = 0; k < 4; k++) { cT[m][n][k] = 0.f; cG[m][n][k] = 0.f; }

    __syncthreads();   // tables ready

    // zero-point term: cT[t][r] = sum_g S[t][g] * z'[r][g]
    #pragma unroll 4
    for (int g = 0; g < NGRP; g++) {
        float sv[4][2];
        #pragma unroll
        for (int m = 0; m < 4; m++) {
            sv[m][0] = Ssm[(m * 16 + trow) * NGRP + g];
            sv[m][1] = Ssm[(m * 16 + trow + 8) * NGRP + g];
        }
        #pragma unroll
        for (int n = 0; n < 2; n++) {
            int rr = warp_n * 16 + n * 8 + tcol;
            float z0 = Zsm[rr * NGRP + g];
            float z1 = Zsm[(rr + 1) * NGRP + g];
            #pragma unroll
            for (int m = 0; m < 4; m++) {
                cT[m][n][0] += sv[m][0] * z0;
                cT[m][n][1] += sv[m][0] * z1;
                cT[m][n][2] += sv[m][1] * z0;
                cT[m][n][3] += sv[m][1] * z1;
            }
        }
    }

    const int lmat = lane >> 3;
    const int lm_off = (((lmat & 1) * 8 + (lane & 7)) * 72 + (lmat >> 1) * 8);

    // ---- main pipelined loop: unrolled x4, static stage pointers ----
    for (int cb = 0; cb < NCHUNK; cb += 4) {
        #pragma unroll
        for (int j = 0; j < 4; j++) {
            const int c = cb + j;
            __syncthreads();   // all warps consumed stage (j+3)&3 (chunk c-1)
            if (c + 3 < NCHUNK)
                prefetch(sm + ((j + 3) & 3) * STG, (c + 3) * 64);
            asm volatile("cp.async.commit_group;");  // always (empty ok)
            asm volatile("cp.async.wait_group 3;");  // chunk c's copies done

            const char* S = sm + j * STG;
            const __half*   A = (const __half*)S;
            const uint32_t* W = (const uint32_t*)(S + 9216);

            #pragma unroll
            for (int ks = 0; ks < 4; ks++) {
                const int kb = ks * 16;
                uint32_t bfrag[2][2];
                #pragma unroll
                for (int n = 0; n < 2; n++) {
                    int rr = warp_n * 16 + n * 8 + trow;
                    uint2 wp = *(const uint2*)(W + rr * 8 + ((2 * ks) ^ (rr & 4)));
                    uint32_t b0 = __byte_perm(wp.x, 0, psel);
                    uint32_t b1 = __byte_perm(wp.y, 0, psel);
                    // fp16(1024+q) = 0x6400 | q ; even col = high nib, odd = low
                    bfrag[n][0] = 0x64006400u | (b0 >> 4) | ((b0 & 15u) << 16);
                    bfrag[n][1] = 0x64006400u | (b1 >> 4) | ((b1 & 15u) << 16);
                }
                #pragma unroll
                for (int m = 0; m < 4; m++) {
                    uint32_t addr = smaddr(A + (m * 16) * 72 + kb + lm_off);
                    uint32_t a0, a1, a2, a3;
                    ldsm4(a0, a1, a2, a3, addr);
                    #pragma unroll
                    for (int n = 0; n < 2; n++)
                        mma_f16(cG[m][n], a0, a1, a2, a3, bfrag[n][0], bfrag[n][1]);
                }
            }

            // group boundary (every 128 k = 2 chunks): fold s_g * P'_g
            if (c & 1) {
                int g = c >> 1;
                #pragma unroll
                for (int n = 0; n < 2; n++) {
                    int rr = warp_n * 16 + n * 8 + tcol;
                    float s0 = Ssc[rr * NGRP + g];
                    float s1 = Ssc[(rr + 1) * NGRP + g];
                    #pragma unroll
                    for (int m = 0; m < 4; m++) {
                        cT[m][n][0] += s0 * cG[m][n][0];
                        cT[m][n][1] += s1 * cG[m][n][1];
                        cT[m][n][2] += s0 * cG[m][n][2];
                        cT[m][n][3] += s1 * cG[m][n][3];
                        cG[m][n][0] = 0.f; cG[m][n][1] = 0.f;
                        cG[m][n][2] = 0.f; cG[m][n][3] = 0.f;
                    }
                }
            }
        }
    }

    // ---- store ----
    #pragma unroll
    for (int m = 0; m < 4; m++) {
        #pragma unroll
        for (int half = 0; half < 2; half++) {
            int tl = m * 16 + trow + half * 8;
            int p = s_pid[tl];
            if (p < 0) continue;
            if (PHASE) {
                float cf = g_coef[p];
                float* Orow = outp + (size_t)(p >> 1) * HID + r0 + warp_n * 16;
                #pragma unroll
                for (int n = 0; n < 2; n++) {
                    atomicAdd(Orow + n * 8 + tcol,     cT[m][n][half * 2 + 0] * cf);
                    atomicAdd(Orow + n * 8 + tcol + 1, cT[m][n][half * 2 + 1] * cf);
                }
            } else {
                float* Crow = g_gu + (size_t)p * TWO_I + r0 + warp_n * 16;
                #pragma unroll
                for (int n = 0; n < 2; n++) {
                    float2 v;
                    v.x = cT[m][n][half * 2 + 0];
                    v.y = cT[m][n][half * 2 + 1];
                    *(float2*)(Crow + n * 8 + tcol) = v;
                }
            }
        }
    }
}

// ---------------------------------------------------------------------------
extern "C" void kernel_launch(void* const* d_in, const int* in_sizes, int n_in,
                              void* d_out, int out_size)
{
    (void)out_size;
    int ix = 0, igup = 1, igs_a = 2, igs_b = 3, idnp = 4, ids_a = 5, ids_b = 6,
        irt_a = 7, irt_b = 8;

    int gu_pair[2] = {-1, -1}, dn_pair[2] = {-1, -1}, rt_pair[2] = {-1, -1};
    int f_x = -1, f_gup = -1, f_dnp = -1;
    for (int i = 0; i < n_in; i++) {
        long long s = in_sizes[i];
        if      (s == 2097152LL)  f_x = i;
        else if (s == 67108864LL) f_gup = i;
        else if (s == 33554432LL) f_dnp = i;
        else if (s == 1048576LL)  { if (gu_pair[0] < 0) gu_pair[0] = i; else gu_pair[1] = i; }
        else if (s == 524288LL)   { if (dn_pair[0] < 0) dn_pair[0] = i; else dn_pair[1] = i; }
        else if (s == 2048LL)     { if (rt_pair[0] < 0) rt_pair[0] = i; else rt_pair[1] = i; }
    }
    if (f_x >= 0 && f_gup >= 0 && f_dnp >= 0 &&
        gu_pair[1] >= 0 && dn_pair[1] >= 0 && rt_pair[1] >= 0) {
        ix = f_x; igup = f_gup; idnp = f_dnp;
        igs_a = gu_pair[0]; igs_b = gu_pair[1];
        ids_a = dn_pair[0]; ids_b = dn_pair[1];
        irt_a = rt_pair[0]; irt_b = rt_pair[1];
    }

    const float*   x    = (const float*)  d_in[ix];
    const uint8_t* gu_p = (const uint8_t*)d_in[igup];
    const float*   gu_a = (const float*)  d_in[igs_a];
    const float*   gu_b = (const float*)  d_in[igs_b];
    const uint8_t* dn_p = (const uint8_t*)d_in[idnp];
    const float*   dn_a = (const float*)  d_in[ids_a];
    const float*   dn_b = (const float*)  d_in[ids_b];
    const void*    rt_a = d_in[irt_a];
    const void*    rt_b = d_in[irt_b];
    float*         out  = (float*)        d_out;

    // dynamic smem: 4 stages + tables
    const int SMEM0 = 4 * 13312 + (64 + 128 + 128) * (HID / GSIZE) * 4 + 256;   // ~74.0 KB
    const int SMEM1 = 4 * 13312 + (64 + 128 + 128) * (INTER / GSIZE) * 4 + 256; // ~94.5 KB
    cudaFuncSetAttribute(mma_gemm<0>, cudaFuncAttributeMaxDynamicSharedMemorySize, SMEM0);
    cudaFuncSetAttribute(mma_gemm<1>, cudaFuncAttributeMaxDynamicSharedMemorySize, SMEM1);

    k_detect<<<1, 32>>>((const uint32_t*)gu_p, gu_a, dn_a, (const uint32_t*)rt_a);
    k_route<<<NPAIR / 256, 256>>>(rt_a, rt_b);
    k_split<<<TOK * (HID / GSIZE) / 8, 256>>>(x, out);

    // grid: (token_block fastest, expert, row_block slowest)
    dim3 g0(NPAIR / 64, EXPERTS, TWO_I / 128);   // (32, 8, 64)
    mma_gemm<0><<<g0, 256, SMEM0>>>(gu_p, gu_a, gu_b, out);

    k_gelu<<<NPAIR * (INTER / GSIZE) / 8, 256>>>();

    dim3 g1(NPAIR / 64, EXPERTS, HID / 128);     // (32, 8, 16)
    mma_gemm<1><<<g1, 256, SMEM1>>>(dn_p, dn_a, dn_b, out);
}

// round 17
// speedup vs baseline: 1.1533x; 1.0422x over previous
#include <cuda_runtime.h>
#include <cuda_fp16.h>
#include <cstdint>

#define EXPERTS 8
#define HID     2048
#define INTER   4096
#define TWO_I   8192
#define TOK     1024
#define NPAIR   2048
#define GSIZE   128

// ---------------------------------------------------------------------------
// Scratch (static __device__ globals)
// ---------------------------------------------------------------------------
__device__ __half g_gu[(size_t)NPAIR * TWO_I];   // gate|up pre-activation, fp16
__device__ __half g_hh[(size_t)NPAIR * INTER];   // h rounded to fp16
__device__ __half g_xh[(size_t)TOK * HID];       // x rounded to fp16
__device__ float  g_S0[TOK][HID / GSIZE];        // group sums of fp16(x)
__device__ float  g_S1[NPAIR][INTER / GSIZE];    // group sums of fp16(h)
__device__ int    g_cnt[EXPERTS];
__device__ int    g_list[EXPERTS][NPAIR];
__device__ float  g_coef[NPAIR];

__device__ int g_wmode, g_swap_gu, g_swap_dn, g_swap_rt;

// ---------------------------------------------------------------------------
// helpers
// ---------------------------------------------------------------------------
__device__ __forceinline__ uint32_t smaddr(const void* p) {
    return (uint32_t)__cvta_generic_to_shared(p);
}
__device__ __forceinline__ void cp16(uint32_t dst, const void* src, int srcbytes) {
    asm volatile("cp.async.cg.shared.global [%0], [%1], 16, %2;"
                 :: "r"(dst), "l"(src), "r"(srcbytes));
}
__device__ __forceinline__ void ldsm4(uint32_t& a0, uint32_t& a1,
                                      uint32_t& a2, uint32_t& a3, uint32_t addr) {
    asm volatile("ldmatrix.sync.aligned.m8n8.x4.shared.b16 {%0,%1,%2,%3}, [%4];"
                 : "=r"(a0), "=r"(a1), "=r"(a2), "=r"(a3) : "r"(addr));
}
__device__ __forceinline__ void mma_f16(float c[4],
    uint32_t a0, uint32_t a1, uint32_t a2, uint32_t a3, uint32_t b0, uint32_t b1)
{
    asm("mma.sync.aligned.m16n8k16.row.col.f32.f16.f16.f32 "
        "{%0,%1,%2,%3}, {%4,%5,%6,%7}, {%8,%9}, {%0,%1,%2,%3};\n"
        : "+f"(c[0]), "+f"(c[1]), "+f"(c[2]), "+f"(c[3])
        : "r"(a0), "r"(a1), "r"(a2), "r"(a3), "r"(b0), "r"(b1));
}

// ---------------------------------------------------------------------------
// Setup kernels
// ---------------------------------------------------------------------------
__global__ void k_detect(const uint32_t* __restrict__ gup,
                         const float* __restrict__ gus_a,
                         const float* __restrict__ dns_a,
                         const uint32_t* __restrict__ rt_a)
{
    if (threadIdx.x < EXPERTS) g_cnt[threadIdx.x] = 0;
    if (threadIdx.x != 0) return;
    int widened = 1;
    for (int i = 0; i < 16; i++)
        if (gup[i] & 0xFFFFFF00u) widened = 0;
    g_wmode = widened;
    int neg = 0;
    for (int i = 0; i < 9; i++) neg += (gus_a[i] < 0.f) ? 1 : 0;
    g_swap_gu = (neg > 4) ? 1 : 0;
    neg = 0;
    for (int i = 0; i < 9; i++) neg += (dns_a[i] < 0.f) ? 1 : 0;
    g_swap_dn = (neg > 4) ? 1 : 0;
    int small = 1;
    for (int i = 0; i < 16; i++)
        if (rt_a[i] >= 256u) small = 0;
    g_swap_rt = small ? 0 : 1;
}

__global__ void k_route(const void* __restrict__ a, const void* __restrict__ b) {
    const int*   ridx = (const int*)  (g_swap_rt ? b : a);
    const float* rw   = (const float*)(g_swap_rt ? a : b);
    int i = blockIdx.x * blockDim.x + threadIdx.x;
    if (i >= NPAIR) return;
    int e = ridx[i];
    int pos = atomicAdd(&g_cnt[e], 1);
    g_list[e][pos] = i;
    g_coef[i] = rw[i];
}

// ---------------------------------------------------------------------------
// x -> fp16 + group sums of the ROUNDED values; also zero `out`.
// ---------------------------------------------------------------------------
__global__ void k_split(const float* __restrict__ x, float* __restrict__ out) {
    int wg   = blockIdx.x * 8 + (threadIdx.x >> 5);
    int lane = threadIdx.x & 31;
    int token = wg >> 4;
    int g     = wg & 15;
    size_t base = (size_t)token * HID + g * GSIZE + lane * 4;
    float4 v = *(const float4*)(x + base);
    __half h0 = __float2half_rn(v.x), h1 = __float2half_rn(v.y);
    __half h2 = __float2half_rn(v.z), h3 = __float2half_rn(v.w);
    ((__half2*)(g_xh + base))[0] = __half2(h0, h1);
    ((__half2*)(g_xh + base))[1] = __half2(h2, h3);
    *(float4*)(out + base) = make_float4(0.f, 0.f, 0.f, 0.f);
    float sum = __half2float(h0) + __half2float(h1)
              + __half2float(h2) + __half2float(h3);
    #pragma unroll
    for (int o = 16; o; o >>= 1) sum += __shfl_xor_sync(0xFFFFFFFFu, sum, o);
    if (lane == 0) g_S0[token][g] = sum;
}

__device__ __forceinline__ float fast_tanh(float x) {
    float e, inv;
    float ax = fabsf(x) * 2.8853900817779268f;
    asm("ex2.approx.f32 %0, %1;" : "=f"(e) : "f"(ax));
    asm("rcp.approx.f32 %0, %1;" : "=f"(inv) : "f"(e + 1.f));
    return copysignf(1.f - 2.f * inv, x);
}

__global__ void k_gelu() {
    int wg   = blockIdx.x * 8 + (threadIdx.x >> 5);
    int lane = threadIdx.x & 31;
    int pid = wg >> 5;
    int g   = wg & 31;
    size_t base = (size_t)pid * INTER + g * GSIZE + lane * 4;
    size_t gub  = (size_t)pid * TWO_I + g * GSIZE + lane * 4;
    uint2 gg2 = *(const uint2*)(g_gu + gub);
    uint2 uu2 = *(const uint2*)(g_gu + gub + INTER);
    float2 g01 = __half22float2(*reinterpret_cast<__half2*>(&gg2.x));
    float2 g23 = __half22float2(*reinterpret_cast<__half2*>(&gg2.y));
    float2 u01 = __half22float2(*reinterpret_cast<__half2*>(&uu2.x));
    float2 u23 = __half22float2(*reinterpret_cast<__half2*>(&uu2.y));
    float gv[4] = {g01.x, g01.y, g23.x, g23.y};
    float uv[4] = {u01.x, u01.y, u23.x, u23.y};
    __half hh[4];
    float sum = 0.f;
    #pragma unroll
    for (int i = 0; i < 4; i++) {
        float t = fast_tanh(0.7978845608028654f * (gv[i] + 0.044715f * gv[i] * gv[i] * gv[i]));
        float h = 0.5f * gv[i] * (1.f + t) * uv[i];
        hh[i] = __float2half_rn(h);
        sum += __half2float(hh[i]);
    }
    ((__half2*)(g_hh + base))[0] = __half2(hh[0], hh[1]);
    ((__half2*)(g_hh + base))[1] = __half2(hh[2], hh[3]);
    #pragma unroll
    for (int o = 16; o; o >>= 1) sum += __shfl_xor_sync(0xFFFFFFFFu, sum, o);
    if (lane == 0) g_S1[pid][g] = sum;
}

// ---------------------------------------------------------------------------
// Pipelined fp16 tensor-core dequant GEMM.
// Block: 64 tokens x 128 rows, 8 warps, warp tile 64 tok x 16 rows.
// PAIR pipeline: 4 stages = 2 pairs of 64-k chunks; ONE barrier + ONE
// wait_group per 128-k pair (pair == quant group). Prime pair0; iter s:
// barrier (pair s+1's stages consumed at s-1) -> prefetch pair s+1 -> commit
// -> wait_group 1 (pair s landed) -> 8 ks-steps -> fold group g=s.
// Weights (q+1024) exact fp16 via PRMT+magic; z' = z - 1024 s.
// PHASE 0 stores fp16 gate|up. PHASE 1 atomicAdd coef*val into `out`
// (exactly 2 contributors per element: deterministic).
// ---------------------------------------------------------------------------
template <int PHASE>
__global__ void __launch_bounds__(256, 2)
mma_gemm(const uint8_t* __restrict__ wpk,
         const float* __restrict__ pa,
         const float* __restrict__ pb,
         float* __restrict__ outp)
{
    constexpr int RTOT  = PHASE ? HID   : TWO_I;
    constexpr int INF   = PHASE ? INTER : HID;
    constexpr int NGRP  = INF / GSIZE;
    constexpr int INFH  = INF / 2;
    constexpr int SHIFT = PHASE ? 0 : 1;
    constexpr int NIT   = INF / 128;      // pair iterations (16 or 32, even)
    constexpr int STG = 13312;            // A 9216 + W 4096

    const int e     = blockIdx.y;
    const int n_tok = g_cnt[e];
    const int t0    = blockIdx.x * 64;    // token-block: fastest dim
    if (t0 >= n_tok) return;
    const int r0   = blockIdx.z * 128;    // weight-row-block: slowest dim
    const int tid  = threadIdx.x;
    const int lane = tid & 31;
    const int wid  = tid >> 5;
    const int warp_n = wid;               // 8 warps x 16 rows
    const int trow = lane >> 2;
    const int tcol = (lane & 3) * 2;
    const uint32_t psel = 0x4440u | (lane & 3);

    const int swp = PHASE ? g_swap_dn : g_swap_gu;
    const float* __restrict__ sc = swp ? pb : pa;
    const float* __restrict__ zp = swp ? pa : pb;
    const int wmode = g_wmode;

    extern __shared__ __align__(16) char sm[];
    float* Ssm   = (float*)(sm + 4 * STG);
    float* Zsm   = Ssm + 64 * NGRP;
    float* Ssc   = Zsm + 128 * NGRP;
    int*   s_pid = (int*)(Ssc + 128 * NGRP);

    const __half* __restrict__ Ag = PHASE ? g_hh : g_xh;
    const float* __restrict__ Sglob = PHASE ? &g_S1[0][0] : &g_S0[0][0];

    if (tid < 64) {
        int slot = t0 + tid;
        s_pid[tid] = (slot < n_tok) ? g_list[e][slot] : -1;
    }
    __syncthreads();

    const size_t wrowbase = (size_t)e * RTOT + r0;

    // ---- hoisted prefetch state ----
    const int tA0 = tid >> 3, tA1 = tA0 + 32;
    const int segA = (tid & 7) * 8;
    const int pA0 = s_pid[tA0], pA1 = s_pid[tA1];
    const __half* asrc0 = Ag + ((pA0 >= 0) ? ((size_t)(pA0 >> SHIFT) * INF + segA) : 0);
    const __half* asrc1 = Ag + ((pA1 >= 0) ? ((size_t)(pA1 >> SHIFT) * INF + segA) : 0);
    const int asz0 = (pA0 >= 0) ? 16 : 0;
    const int asz1 = (pA1 >= 0) ? 16 : 0;
    const uint32_t adst0 = (uint32_t)(tA0 * 144 + (tid & 7) * 16);
    const uint32_t adst1 = (uint32_t)(tA1 * 144 + (tid & 7) * 16);
    const int rowW = tid >> 3;
    const int wcW  = tid & 7;
    const uint32_t we0 = (uint32_t)((wrowbase + rowW) * INFH) + wcW * 4;
    const uint32_t wdst0 = 9216u + (uint32_t)((rowW * 8 + (wcW ^ (rowW & 4))) * 4);
    const uint32_t* __restrict__ wsrc32 = (const uint32_t*)wpk;

    auto prefetch = [&](char* S, int h0) {
        cp16(smaddr(S) + adst0, asrc0 + h0, asz0);
        cp16(smaddr(S) + adst1, asrc1 + h0, asz1);
        if (wmode == 0) {
            uint32_t* W = (uint32_t*)(S + 9216);
            int row = tid >> 1;
            int u   = tid & 1;
            const uint8_t* src = wpk + (wrowbase + row) * INFH + (h0 >> 1) + u * 16;
            cp16(smaddr(W + row * 8 + ((u << 2) ^ (row & 4))), src, 16);
        } else {
            const uint32_t* src = wsrc32 + we0 + (h0 >> 1);
            #pragma unroll
            for (int i = 0; i < 4; i++) {
                uint4 v4 = *(const uint4*)(src + (uint32_t)i * (32u * INFH));
                uint32_t b01 = __byte_perm(v4.x, v4.y, 0x0040);
                uint32_t b23 = __byte_perm(v4.z, v4.w, 0x0040);
                *(uint32_t*)(S + wdst0 + i * 1024) = __byte_perm(b01, b23, 0x5410);
            }
        }
    };

    // prime pair 0 (chunks 0,1 -> stages 0,1), one commit group
    prefetch(sm + 0 * STG, 0);
    prefetch(sm + 1 * STG, 64);
    asm volatile("cp.async.commit_group;");

    // ---- prologue tables ----
    for (int i = tid; i < 64 * NGRP; i += 256) {
        int t = i / NGRP, g = i % NGRP;
        int p = s_pid[t];
        Ssm[i] = (p >= 0) ? Sglob[(size_t)(p >> SHIFT) * NGRP + g] : 0.f;
    }
    for (int i = tid; i < 128 * NGRP; i += 256) {
        int r = i / NGRP, g = i % NGRP;
        size_t idx = (wrowbase + r) * NGRP + g;
        float s = sc[idx];
        Zsm[i] = zp[idx] - 1024.f * s;
        Ssc[i] = s;
    }

    float cT[4][2][4], cG[4][2][4];
    #pragma unroll
    for (int m = 0; m < 4; m++)
        #pragma unroll
        for (int n = 0; n < 2; n++)
            #pragma unroll
            for (int k = 0; k < 4; k++) { cT[m][n][k] = 0.f; cG[m][n][k] = 0.f; }

    __syncthreads();   // tables ready

    // zero-point term: cT[t][r] = sum_g S[t][g] * z'[r][g]
    #pragma unroll 4
    for (int g = 0; g < NGRP; g++) {
        float sv[4][2];
        #pragma unroll
        for (int m = 0; m < 4; m++) {
            sv[m][0] = Ssm[(m * 16 + trow) * NGRP + g];
            sv[m][1] = Ssm[(m * 16 + trow + 8) * NGRP + g];
        }
        #pragma unroll
        for (int n = 0; n < 2; n++) {
            int rr = warp_n * 16 + n * 8 + tcol;
            float z0 = Zsm[rr * NGRP + g];
            float z1 = Zsm[(rr + 1) * NGRP + g];
            #pragma unroll
            for (int m = 0; m < 4; m++) {
                cT[m][n][0] += sv[m][0] * z0;
                cT[m][n][1] += sv[m][0] * z1;
                cT[m][n][2] += sv[m][1] * z0;
                cT[m][n][3] += sv[m][1] * z1;
            }
        }
    }

    const int lmat = lane >> 3;
    const int lm_off = (((lmat & 1) * 8 + (lane & 7)) * 72 + (lmat >> 1) * 8);

    // ---- main pair-pipelined loop: unrolled x2, static stage pointers ----
    for (int sb = 0; sb < NIT; sb += 2) {
        #pragma unroll
        for (int pj = 0; pj < 2; pj++) {
            const int s = sb + pj;
            __syncthreads();   // pair (s+1)'s stages were consumed at iter s-1
            if (s + 1 < NIT) {
                char* T0 = sm + ((pj ^ 1) * 2 + 0) * STG;
                char* T1 = sm + ((pj ^ 1) * 2 + 1) * STG;
                prefetch(T0, (s + 1) * 128);
                prefetch(T1, (s + 1) * 128 + 64);
            }
            asm volatile("cp.async.commit_group;");  // always (empty ok)
            asm volatile("cp.async.wait_group 1;");  // pair s landed

            // consume the pair's 2 chunks = one full quant group (128 k)
            #pragma unroll
            for (int half_c = 0; half_c < 2; half_c++) {
                const char* S = sm + (pj * 2 + half_c) * STG;
                const __half*   A = (const __half*)S;
                const uint32_t* W = (const uint32_t*)(S + 9216);
                #pragma unroll
                for (int ks = 0; ks < 4; ks++) {
                    const int kb = ks * 16;
                    uint32_t bfrag[2][2];
                    #pragma unroll
                    for (int n = 0; n < 2; n++) {
                        int rr = warp_n * 16 + n * 8 + trow;
                        uint2 wp = *(const uint2*)(W + rr * 8 + ((2 * ks) ^ (rr & 4)));
                        uint32_t b0 = __byte_perm(wp.x, 0, psel);
                        uint32_t b1 = __byte_perm(wp.y, 0, psel);
                        bfrag[n][0] = 0x64006400u | (b0 >> 4) | ((b0 & 15u) << 16);
                        bfrag[n][1] = 0x64006400u | (b1 >> 4) | ((b1 & 15u) << 16);
                    }
                    #pragma unroll
                    for (int m = 0; m < 4; m++) {
                        uint32_t addr = smaddr(A + (m * 16) * 72 + kb + lm_off);
                        uint32_t a0, a1, a2, a3;
                        ldsm4(a0, a1, a2, a3, addr);
                        #pragma unroll
                        for (int n = 0; n < 2; n++)
                            mma_f16(cG[m][n], a0, a1, a2, a3, bfrag[n][0], bfrag[n][1]);
                    }
                }
            }

            // fold group g = s
            #pragma unroll
            for (int n = 0; n < 2; n++) {
                int rr = warp_n * 16 + n * 8 + tcol;
                float s0 = Ssc[rr * NGRP + s];
                float s1 = Ssc[(rr + 1) * NGRP + s];
                #pragma unroll
                for (int m = 0; m < 4; m++) {
                    cT[m][n][0] += s0 * cG[m][n][0];
                    cT[m][n][1] += s1 * cG[m][n][1];
                    cT[m][n][2] += s0 * cG[m][n][2];
                    cT[m][n][3] += s1 * cG[m][n][3];
                    cG[m][n][0] = 0.f; cG[m][n][1] = 0.f;
                    cG[m][n][2] = 0.f; cG[m][n][3] = 0.f;
                }
            }
        }
    }

    // ---- store ----
    #pragma unroll
    for (int m = 0; m < 4; m++) {
        #pragma unroll
        for (int half = 0; half < 2; half++) {
            int tl = m * 16 + trow + half * 8;
            int p = s_pid[tl];
            if (p < 0) continue;
            if (PHASE) {
                float cf = g_coef[p];
                float* Orow = outp + (size_t)(p >> 1) * HID + r0 + warp_n * 16;
                #pragma unroll
                for (int n = 0; n < 2; n++) {
                    atomicAdd(Orow + n * 8 + tcol,     cT[m][n][half * 2 + 0] * cf);
                    atomicAdd(Orow + n * 8 + tcol + 1, cT[m][n][half * 2 + 1] * cf);
                }
            } else {
                __half* Crow = g_gu + (size_t)p * TWO_I + r0 + warp_n * 16;
                #pragma unroll
                for (int n = 0; n < 2; n++) {
                    __half2 hv(__float2half_rn(cT[m][n][half * 2 + 0]),
                               __float2half_rn(cT[m][n][half * 2 + 1]));
                    *(uint32_t*)(Crow + n * 8 + tcol) = *reinterpret_cast<uint32_t*>(&hv);
                }
            }
        }
    }
}

// ---------------------------------------------------------------------------
extern "C" void kernel_launch(void* const* d_in, const int* in_sizes, int n_in,
                              void* d_out, int out_size)
{
    (void)out_size;
    int ix = 0, igup = 1, igs_a = 2, igs_b = 3, idnp = 4, ids_a = 5, ids_b = 6,
        irt_a = 7, irt_b = 8;

    int gu_pair[2] = {-1, -1}, dn_pair[2] = {-1, -1}, rt_pair[2] = {-1, -1};
    int f_x = -1, f_gup = -1, f_dnp = -1;
    for (int i = 0; i < n_in; i++) {
        long long s = in_sizes[i];
        if      (s == 2097152LL)  f_x = i;
        else if (s == 67108864LL) f_gup = i;
        else if (s == 33554432LL) f_dnp = i;
        else if (s == 1048576LL)  { if (gu_pair[0] < 0) gu_pair[0] = i; else gu_pair[1] = i; }
        else if (s == 524288LL)   { if (dn_pair[0] < 0) dn_pair[0] = i; else dn_pair[1] = i; }
        else if (s == 2048LL)     { if (rt_pair[0] < 0) rt_pair[0] = i; else rt_pair[1] = i; }
    }
    if (f_x >= 0 && f_gup >= 0 && f_dnp >= 0 &&
        gu_pair[1] >= 0 && dn_pair[1] >= 0 && rt_pair[1] >= 0) {
        ix = f_x; igup = f_gup; idnp = f_dnp;
        igs_a = gu_pair[0]; igs_b = gu_pair[1];
        ids_a = dn_pair[0]; ids_b = dn_pair[1];
        irt_a = rt_pair[0]; irt_b = rt_pair[1];
    }

    const float*   x    = (const float*)  d_in[ix];
    const uint8_t* gu_p = (const uint8_t*)d_in[igup];
    const float*   gu_a = (const float*)  d_in[igs_a];
    const float*   gu_b = (const float*)  d_in[igs_b];
    const uint8_t* dn_p = (const uint8_t*)d_in[idnp];
    const float*   dn_a = (const float*)  d_in[ids_a];
    const float*   dn_b = (const float*)  d_in[ids_b];
    const void*    rt_a = d_in[irt_a];
    const void*    rt_b = d_in[irt_b];
    float*         out  = (float*)        d_out;

    const int SMEM0 = 4 * 13312 + (64 + 128 + 128) * (HID / GSIZE) * 4 + 256;   // ~74.0 KB
    const int SMEM1 = 4 * 13312 + (64 + 128 + 128) * (INTER / GSIZE) * 4 + 256; // ~94.5 KB
    cudaFuncSetAttribute(mma_gemm<0>, cudaFuncAttributeMaxDynamicSharedMemorySize, SMEM0);
    cudaFuncSetAttribute(mma_gemm<1>, cudaFuncAttributeMaxDynamicSharedMemorySize, SMEM1);

    k_detect<<<1, 32>>>((const uint32_t*)gu_p, gu_a, dn_a, (const uint32_t*)rt_a);
    k_route<<<NPAIR / 256, 256>>>(rt_a, rt_b);
    k_split<<<TOK * (HID / GSIZE) / 8, 256>>>(x, out);

    // grid: (token_block fastest, expert, row_block slowest)
    dim3 g0(NPAIR / 64, EXPERTS, TWO_I / 128);   // (32, 8, 64)
    mma_gemm<0><<<g0, 256, SMEM0>>>(gu_p, gu_a, gu_b, out);

    k_gelu<<<NPAIR * (INTER / GSIZE) / 8, 256>>>();

    dim3 g1(NPAIR / 64, EXPERTS, HID / 128);     // (32, 8, 16)
    mma_gemm<1><<<g1, 256, SMEM1>>>(dn_p, dn_a, dn_b, out);
}